// round 2
// baseline (speedup 1.0000x reference)
#include <cuda_runtime.h>
#include <float.h>

#define D 128
#define KN 32
#define MAXN 50000

// scratch for projected features h = feat @ weight  (bias added at the end)
__device__ float g_h[(size_t)MAXN * D];
__device__ int   g_idx_is64;

// ---------------------------------------------------------------------------
// Detect whether top_k_idx is stored as int64 or int32.
// int64 view of int32 data yields values >= 2^32 (next index in the hi word)
// almost surely; genuine int64 data stays in [-1, n).
// ---------------------------------------------------------------------------
__global__ void detect_kernel(const long long* __restrict__ idx64,
                              int n_elems, int n) {
    if (threadIdx.x != 0 || blockIdx.x != 0) return;
    int cnt = n_elems / 2;            // safe to read this many int64 even if int32
    if (cnt > 256) cnt = 256;
    int ok64 = 1;
    for (int i = 0; i < cnt; ++i) {
        long long v = idx64[i];
        if (v < -1 || v >= (long long)n) { ok64 = 0; break; }
    }
    g_idx_is64 = ok64;
}

// ---------------------------------------------------------------------------
// Kernel A: h[n, 128] = feat[n, 128] @ weight[128, 128]
// ---------------------------------------------------------------------------
__global__ __launch_bounds__(128) void proj_kernel(const float* __restrict__ feat,
                                                   const float* __restrict__ weight,
                                                   int n) {
    __shared__ float sf[32][D];
    const int row0 = blockIdx.x * 32;
    const int tid  = threadIdx.x;

#pragma unroll
    for (int it = 0; it < 8; ++it) {
        int lin = it * 128 + tid;
        int r = lin >> 5, c = lin & 31;
        int row = row0 + r;
        float4 v = make_float4(0.f, 0.f, 0.f, 0.f);
        if (row < n) v = reinterpret_cast<const float4*>(feat)[(size_t)row * 32 + c];
        *reinterpret_cast<float4*>(&sf[r][c * 4]) = v;
    }
    __syncthreads();

    const int c = tid;  // output column
    float acc[32];
#pragma unroll
    for (int r = 0; r < 32; ++r) acc[r] = 0.f;

#pragma unroll 4
    for (int kt = 0; kt < D; kt += 8) {
        float w[8];
#pragma unroll
        for (int j = 0; j < 8; ++j) w[j] = weight[(kt + j) * D + c];
#pragma unroll
        for (int r = 0; r < 32; ++r) {
            float4 f0 = *reinterpret_cast<const float4*>(&sf[r][kt]);
            float4 f1 = *reinterpret_cast<const float4*>(&sf[r][kt + 4]);
            acc[r] += f0.x * w[0] + f0.y * w[1] + f0.z * w[2] + f0.w * w[3]
                    + f1.x * w[4] + f1.y * w[5] + f1.z * w[6] + f1.w * w[7];
        }
    }
#pragma unroll
    for (int r = 0; r < 32; ++r) {
        int row = row0 + r;
        if (row < n) g_h[(size_t)row * D + c] = acc[r];
    }
}

// ---------------------------------------------------------------------------
// Kernel B: per-node soft-medoid aggregation. One 128-thread block per node.
// ---------------------------------------------------------------------------
__device__ __forceinline__ float warp_max32(float v) {
#pragma unroll
    for (int off = 16; off > 0; off >>= 1)
        v = fmaxf(v, __shfl_xor_sync(0xffffffffu, v, off));
    return v;
}
__device__ __forceinline__ float warp_sum32(float v) {
#pragma unroll
    for (int off = 16; off > 0; off >>= 1)
        v += __shfl_xor_sync(0xffffffffu, v, off);
    return v;
}

__global__ __launch_bounds__(128) void node_kernel(const void* __restrict__ top_k_idx,
                                                   const float* __restrict__ top_k_w,
                                                   const float* __restrict__ bias,
                                                   float* __restrict__ out,
                                                   int n) {
    // fk row stride = 33 float4 = 132 floats (pad keeps LDS.128 conflict-free)
    __shared__ float4 fk4[KN][33];
    __shared__ float  gram[KN][33];   // later overwritten with dist
    __shared__ float  s_w[KN], s_sq[KN], s_r[KN];
    __shared__ int    s_idx[KN], s_mask[KN];

    const int node = blockIdx.x;
    const int tid  = threadIdx.x;
    const int lane = tid & 31;
    const int warp = tid >> 5;

    if (tid < KN) {
        long long id;
        if (g_idx_is64) {
            id = reinterpret_cast<const long long*>(top_k_idx)[(size_t)node * KN + tid];
        } else {
            id = (long long)reinterpret_cast<const int*>(top_k_idx)[(size_t)node * KN + tid];
        }
        int m = (id < 0);
        int ii = m ? 0 : (int)id;
        if (ii >= n) ii = 0;          // safety clamp (never expected to trigger)
        s_mask[tid] = m;
        s_idx[tid]  = ii;
        s_w[tid]    = m ? 0.f : top_k_w[(size_t)node * KN + tid];
    }
    __syncthreads();

    // ---- gather 32 neighbor rows (1024 float4) ----
#pragma unroll
    for (int it = 0; it < 8; ++it) {
        int lin = it * 128 + tid;
        int r = lin >> 5, c = lin & 31;
        const float4* src = reinterpret_cast<const float4*>(g_h + (size_t)s_idx[r] * D);
        fk4[r][c] = src[c];
    }
    __syncthreads();

    // ---- Gram: gram[k][m] = dot(fk[k], fk[m]).  m = lane, k = warp*8..+7 ----
    {
        float acc0 = 0.f, acc1 = 0.f, acc2 = 0.f, acc3 = 0.f;
        float acc4 = 0.f, acc5 = 0.f, acc6 = 0.f, acc7 = 0.f;
        const int kb = warp * 8;
#pragma unroll 8
        for (int c = 0; c < 32; ++c) {
            float4 b = fk4[lane][c];
            float4 a;
            a = fk4[kb + 0][c]; acc0 += a.x*b.x + a.y*b.y + a.z*b.z + a.w*b.w;
            a = fk4[kb + 1][c]; acc1 += a.x*b.x + a.y*b.y + a.z*b.z + a.w*b.w;
            a = fk4[kb + 2][c]; acc2 += a.x*b.x + a.y*b.y + a.z*b.z + a.w*b.w;
            a = fk4[kb + 3][c]; acc3 += a.x*b.x + a.y*b.y + a.z*b.z + a.w*b.w;
            a = fk4[kb + 4][c]; acc4 += a.x*b.x + a.y*b.y + a.z*b.z + a.w*b.w;
            a = fk4[kb + 5][c]; acc5 += a.x*b.x + a.y*b.y + a.z*b.z + a.w*b.w;
            a = fk4[kb + 6][c]; acc6 += a.x*b.x + a.y*b.y + a.z*b.z + a.w*b.w;
            a = fk4[kb + 7][c]; acc7 += a.x*b.x + a.y*b.y + a.z*b.z + a.w*b.w;
        }
        gram[kb + 0][lane] = acc0;
        gram[kb + 1][lane] = acc1;
        gram[kb + 2][lane] = acc2;
        gram[kb + 3][lane] = acc3;
        gram[kb + 4][lane] = acc4;
        gram[kb + 5][lane] = acc5;
        gram[kb + 6][lane] = acc6;
        gram[kb + 7][lane] = acc7;
    }
    __syncthreads();

    // ---- squared norms from the diagonal ----
    if (tid < KN) s_sq[tid] = gram[tid][tid];
    __syncthreads();

    // ---- distances (in place over gram) ----
#pragma unroll
    for (int e = 0; e < 8; ++e) {
        int lin = e * 128 + tid;
        int k = lin >> 5, m = lin & 31;
        float d2 = s_sq[k] + s_sq[m] - 2.f * gram[k][m];
        float dv = (d2 > 0.f) ? sqrtf(d2) : 0.f;
        if (s_mask[k] | s_mask[m]) dv = 0.f;
        gram[k][m] = dv;
    }
    __syncthreads();

    // ---- dagg + softmax + weight correction (warp 0) ----
    if (tid < KN) {
        float s = 0.f;
#pragma unroll
        for (int m = 0; m < KN; ++m) s += s_w[m] * gram[tid][m];
        if (s_mask[tid] || !isfinite(s)) s = FLT_MAX;

        float neg = -s;  // TEMPERATURE = 1
        float mx  = warp_max32(neg);
        float ev  = __expf(neg - mx);
        float se  = warp_sum32(ev);
        float r   = ev / se;
        r *= s_w[tid];
        float sr = warp_sum32(r);
        r = r / sr;
        if (s_mask[tid]) r = 0.f;
        s_r[tid] = r;
    }
    __syncthreads();

    // ---- out[node][d] = sum_k r[k] * fk[k][d] + bias[d] ----
    {
        const float* fkf = reinterpret_cast<const float*>(fk4);  // row stride 132
        float acc = 0.f;
#pragma unroll
        for (int k = 0; k < KN; ++k) acc += s_r[k] * fkf[k * 132 + tid];
        out[(size_t)node * D + tid] = acc + bias[tid];
    }
}

// ---------------------------------------------------------------------------
extern "C" void kernel_launch(void* const* d_in, const int* in_sizes, int n_in,
                              void* d_out, int out_size) {
    const float* feat   = (const float*)d_in[0];      // [n, 128]
    const float* weight = (const float*)d_in[1];      // [128, 128]
    const float* bias   = (const float*)d_in[2];      // [128]
    const float* tkw    = (const float*)d_in[3];      // [n, 32]
    const void*  tki    = d_in[4];                    // [n, 32] int32 or int64

    float* out = (float*)d_out;
    const int n = in_sizes[0] / D;

    detect_kernel<<<1, 1>>>((const long long*)tki, in_sizes[4], n);
    proj_kernel<<<(n + 31) / 32, 128>>>(feat, weight, n);
    node_kernel<<<n, 128>>>(tki, tkw, bias, out, n);
}

// round 4
// speedup vs baseline: 1.0752x; 1.0752x over previous
#include <cuda_runtime.h>
#include <float.h>

#define D 128
#define KN 32
#define MAXN 50000

// scratch for projected features h = feat @ weight  (bias added at the end)
__device__ float g_h[(size_t)MAXN * D];
__device__ int   g_idx_is64;

// ---- packed fp32x2 helpers (sm_103a FFMA2 via PTX) ----
__device__ __forceinline__ void fma2(unsigned long long& d,
                                     unsigned long long a,
                                     unsigned long long b) {
    asm("fma.rn.f32x2 %0, %1, %2, %0;" : "+l"(d) : "l"(a), "l"(b));
}
__device__ __forceinline__ unsigned long long pack2(float lo, float hi) {
    unsigned long long r;
    asm("mov.b64 %0, {%1, %2};" : "=l"(r) : "f"(lo), "f"(hi));
    return r;
}
__device__ __forceinline__ float f2sum(unsigned long long v) {
    float lo = __uint_as_float((unsigned)(v & 0xffffffffull));
    float hi = __uint_as_float((unsigned)(v >> 32));
    return lo + hi;
}

// ---------------------------------------------------------------------------
// Detect whether top_k_idx is stored as int64 or int32 (parallel, 1 warp).
// int64 view of int32 data yields values >= 2^32 almost surely.
// ---------------------------------------------------------------------------
__global__ void detect_kernel(const long long* __restrict__ idx64,
                              int n_elems, int n) {
    int cnt = n_elems / 2;
    if (cnt > 32) cnt = 32;
    int lane = threadIdx.x;
    int bad = 0;
    if (lane < cnt) {
        long long v = idx64[lane];
        bad = (v < -1 || v >= (long long)n);
    }
    unsigned any_bad = __ballot_sync(0xffffffffu, bad);
    if (lane == 0) g_idx_is64 = (any_bad == 0u);
}

// ---------------------------------------------------------------------------
// Kernel A: h[n, 128] = feat[n, 128] @ weight[128, 128]   (f32x2 inner loop)
// ---------------------------------------------------------------------------
__global__ __launch_bounds__(128) void proj_kernel(const float* __restrict__ feat,
                                                   const float* __restrict__ weight,
                                                   int n) {
    __shared__ float sf[32][D];
    const int row0 = blockIdx.x * 32;
    const int tid  = threadIdx.x;

#pragma unroll
    for (int it = 0; it < 8; ++it) {
        int lin = it * 128 + tid;
        int r = lin >> 5, c = lin & 31;
        int row = row0 + r;
        float4 v = make_float4(0.f, 0.f, 0.f, 0.f);
        if (row < n) v = reinterpret_cast<const float4*>(feat)[(size_t)row * 32 + c];
        *reinterpret_cast<float4*>(&sf[r][c * 4]) = v;
    }
    __syncthreads();

    const int c = tid;  // output column
    unsigned long long acc[32];
#pragma unroll
    for (int r = 0; r < 32; ++r) acc[r] = 0ull;

#pragma unroll 4
    for (int kt = 0; kt < D; kt += 8) {
        float w0 = weight[(kt + 0) * D + c];
        float w1 = weight[(kt + 1) * D + c];
        float w2 = weight[(kt + 2) * D + c];
        float w3 = weight[(kt + 3) * D + c];
        float w4 = weight[(kt + 4) * D + c];
        float w5 = weight[(kt + 5) * D + c];
        float w6 = weight[(kt + 6) * D + c];
        float w7 = weight[(kt + 7) * D + c];
        unsigned long long p01 = pack2(w0, w1);
        unsigned long long p23 = pack2(w2, w3);
        unsigned long long p45 = pack2(w4, w5);
        unsigned long long p67 = pack2(w6, w7);
#pragma unroll
        for (int r = 0; r < 32; ++r) {
            ulonglong2 f01 = *reinterpret_cast<const ulonglong2*>(&sf[r][kt]);
            ulonglong2 f45 = *reinterpret_cast<const ulonglong2*>(&sf[r][kt + 4]);
            fma2(acc[r], f01.x, p01);
            fma2(acc[r], f01.y, p23);
            fma2(acc[r], f45.x, p45);
            fma2(acc[r], f45.y, p67);
        }
    }
#pragma unroll
    for (int r = 0; r < 32; ++r) {
        int row = row0 + r;
        if (row < n) g_h[(size_t)row * D + c] = f2sum(acc[r]);
    }
}

// ---------------------------------------------------------------------------
// Kernel B: per-node soft-medoid aggregation. One 128-thread block per node.
// ---------------------------------------------------------------------------
__device__ __forceinline__ float warp_max32(float v) {
#pragma unroll
    for (int off = 16; off > 0; off >>= 1)
        v = fmaxf(v, __shfl_xor_sync(0xffffffffu, v, off));
    return v;
}
__device__ __forceinline__ float warp_sum32(float v) {
#pragma unroll
    for (int off = 16; off > 0; off >>= 1)
        v += __shfl_xor_sync(0xffffffffu, v, off);
    return v;
}

__global__ __launch_bounds__(128) void node_kernel(const void* __restrict__ top_k_idx,
                                                   const float* __restrict__ top_k_w,
                                                   const float* __restrict__ bias,
                                                   float* __restrict__ out,
                                                   int n) {
    // fk row stride = 33 float4 = 132 floats (pad keeps LDS.128 conflict-free)
    __shared__ float4 fk4[KN][33];
    __shared__ float  gram[KN][33];   // later overwritten with dist
    __shared__ float  s_w[KN], s_sq[KN], s_r[KN];
    __shared__ int    s_idx[KN], s_mask[KN];

    const int node = blockIdx.x;
    const int tid  = threadIdx.x;
    const int lane = tid & 31;
    const int warp = tid >> 5;

    if (tid < KN) {
        long long id;
        if (g_idx_is64) {
            id = reinterpret_cast<const long long*>(top_k_idx)[(size_t)node * KN + tid];
        } else {
            id = (long long)reinterpret_cast<const int*>(top_k_idx)[(size_t)node * KN + tid];
        }
        int m = (id < 0);
        int ii = m ? 0 : (int)id;
        if (ii >= n) ii = 0;          // safety clamp
        s_mask[tid] = m;
        s_idx[tid]  = ii;
        s_w[tid]    = m ? 0.f : top_k_w[(size_t)node * KN + tid];
    }
    __syncthreads();

    // ---- gather 32 neighbor rows (1024 float4) ----
#pragma unroll
    for (int it = 0; it < 8; ++it) {
        int lin = it * 128 + tid;
        int r = lin >> 5, c = lin & 31;
        const float4* src = reinterpret_cast<const float4*>(g_h + (size_t)s_idx[r] * D);
        fk4[r][c] = src[c];
    }
    __syncthreads();

    // ---- Gram via f32x2: gram[k][m] = dot(fk[k], fk[m]); m = lane, k = warp*8..+7
    {
        unsigned long long acc[8];
#pragma unroll
        for (int j = 0; j < 8; ++j) acc[j] = 0ull;
        const int kb = warp * 8;
        const ulonglong2* brow = reinterpret_cast<const ulonglong2*>(&fk4[lane][0]);
#pragma unroll 8
        for (int c = 0; c < 32; ++c) {
            ulonglong2 b = brow[c];
#pragma unroll
            for (int j = 0; j < 8; ++j) {
                ulonglong2 a = reinterpret_cast<const ulonglong2*>(&fk4[kb + j][0])[c];
                fma2(acc[j], a.x, b.x);
                fma2(acc[j], a.y, b.y);
            }
        }
#pragma unroll
        for (int j = 0; j < 8; ++j) gram[kb + j][lane] = f2sum(acc[j]);
    }
    __syncthreads();

    // ---- squared norms from the diagonal ----
    if (tid < KN) s_sq[tid] = gram[tid][tid];
    __syncthreads();

    // ---- distances (in place over gram) ----
#pragma unroll
    for (int e = 0; e < 8; ++e) {
        int lin = e * 128 + tid;
        int k = lin >> 5, m = lin & 31;
        float d2 = s_sq[k] + s_sq[m] - 2.f * gram[k][m];
        float dv = (d2 > 0.f) ? sqrtf(d2) : 0.f;
        if (s_mask[k] | s_mask[m]) dv = 0.f;
        gram[k][m] = dv;
    }
    __syncthreads();

    // ---- dagg + softmax + weight correction (warp 0) ----
    if (tid < KN) {
        float s = 0.f;
#pragma unroll
        for (int m = 0; m < KN; ++m) s += s_w[m] * gram[tid][m];
        if (s_mask[tid] || !isfinite(s)) s = FLT_MAX;

        float neg = -s;  // TEMPERATURE = 1
        float mx  = warp_max32(neg);
        float ev  = __expf(neg - mx);
        float se  = warp_sum32(ev);
        float r   = ev / se;
        r *= s_w[tid];
        float sr = warp_sum32(r);
        r = r / sr;
        if (s_mask[tid]) r = 0.f;
        s_r[tid] = r;
    }
    __syncthreads();

    // ---- out[node][d] = sum_k r[k] * fk[k][d] + bias[d] ----
    {
        const float* fkf = reinterpret_cast<const float*>(fk4);  // row stride 132
        float acc = 0.f;
#pragma unroll
        for (int k = 0; k < KN; ++k) acc += s_r[k] * fkf[k * 132 + tid];
        out[(size_t)node * D + tid] = acc + bias[tid];
    }
}

// ---------------------------------------------------------------------------
extern "C" void kernel_launch(void* const* d_in, const int* in_sizes, int n_in,
                              void* d_out, int out_size) {
    const float* feat   = (const float*)d_in[0];      // [n, 128]
    const float* weight = (const float*)d_in[1];      // [128, 128]
    const float* bias   = (const float*)d_in[2];      // [128]
    const float* tkw    = (const float*)d_in[3];      // [n, 32]
    const void*  tki    = d_in[4];                    // [n, 32] int32 or int64

    float* out = (float*)d_out;
    const int n = in_sizes[0] / D;

    detect_kernel<<<1, 32>>>((const long long*)tki, in_sizes[4], n);
    proj_kernel<<<(n + 31) / 32, 128>>>(feat, weight, n);
    node_kernel<<<n, 128>>>(tki, tkw, bias, out, n);
}

// round 6
// speedup vs baseline: 1.7573x; 1.6344x over previous
#include <cuda_runtime.h>
#include <cuda_bf16.h>
#include <float.h>

#define D 128
#define KN 32
#define MAXN 50000
#define ASTRIDE 136   // bf16 elements per row (128 + 8 pad), 272 B

// scratch for projected features h = feat @ weight
__device__ float g_h[(size_t)MAXN * D];

// ---- packed fp32x2 helpers (proj kernel) ----
__device__ __forceinline__ void fma2(unsigned long long& d,
                                     unsigned long long a,
                                     unsigned long long b) {
    asm("fma.rn.f32x2 %0, %1, %2, %0;" : "+l"(d) : "l"(a), "l"(b));
}
__device__ __forceinline__ unsigned long long pack2(float lo, float hi) {
    unsigned long long r;
    asm("mov.b64 %0, {%1, %2};" : "=l"(r) : "f"(lo), "f"(hi));
    return r;
}
__device__ __forceinline__ float f2sum(unsigned long long v) {
    float lo = __uint_as_float((unsigned)(v & 0xffffffffull));
    float hi = __uint_as_float((unsigned)(v >> 32));
    return lo + hi;
}

// ---- mma / ldmatrix helpers ----
__device__ __forceinline__ void ldm_x4(unsigned (&r)[4], unsigned addr) {
    asm volatile("ldmatrix.sync.aligned.m8n8.x4.shared.b16 {%0,%1,%2,%3}, [%4];"
                 : "=r"(r[0]), "=r"(r[1]), "=r"(r[2]), "=r"(r[3]) : "r"(addr));
}
__device__ __forceinline__ void ldm_x2(unsigned (&r)[2], unsigned addr) {
    asm volatile("ldmatrix.sync.aligned.m8n8.x2.shared.b16 {%0,%1}, [%2];"
                 : "=r"(r[0]), "=r"(r[1]) : "r"(addr));
}
__device__ __forceinline__ void mma_bf16(float (&d)[4], const unsigned (&a)[4],
                                         const unsigned (&b)[2]) {
    asm volatile(
        "mma.sync.aligned.m16n8k16.row.col.f32.bf16.bf16.f32 "
        "{%0,%1,%2,%3},{%4,%5,%6,%7},{%8,%9},{%0,%1,%2,%3};"
        : "+f"(d[0]), "+f"(d[1]), "+f"(d[2]), "+f"(d[3])
        : "r"(a[0]), "r"(a[1]), "r"(a[2]), "r"(a[3]), "r"(b[0]), "r"(b[1]));
}

// ---------------------------------------------------------------------------
// Kernel A: h[n, 128] = feat[n, 128] @ weight[128, 128]   (f32x2 inner loop)
// ---------------------------------------------------------------------------
__global__ __launch_bounds__(128) void proj_kernel(const float* __restrict__ feat,
                                                   const float* __restrict__ weight,
                                                   int n) {
    __shared__ float sf[32][D];
    const int row0 = blockIdx.x * 32;
    const int tid  = threadIdx.x;

#pragma unroll
    for (int it = 0; it < 8; ++it) {
        int lin = it * 128 + tid;
        int r = lin >> 5, c = lin & 31;
        int row = row0 + r;
        float4 v = make_float4(0.f, 0.f, 0.f, 0.f);
        if (row < n) v = reinterpret_cast<const float4*>(feat)[(size_t)row * 32 + c];
        *reinterpret_cast<float4*>(&sf[r][c * 4]) = v;
    }
    __syncthreads();

    const int c = tid;
    unsigned long long acc[32];
#pragma unroll
    for (int r = 0; r < 32; ++r) acc[r] = 0ull;

#pragma unroll 4
    for (int kt = 0; kt < D; kt += 8) {
        float w0 = weight[(kt + 0) * D + c];
        float w1 = weight[(kt + 1) * D + c];
        float w2 = weight[(kt + 2) * D + c];
        float w3 = weight[(kt + 3) * D + c];
        float w4 = weight[(kt + 4) * D + c];
        float w5 = weight[(kt + 5) * D + c];
        float w6 = weight[(kt + 6) * D + c];
        float w7 = weight[(kt + 7) * D + c];
        unsigned long long p01 = pack2(w0, w1);
        unsigned long long p23 = pack2(w2, w3);
        unsigned long long p45 = pack2(w4, w5);
        unsigned long long p67 = pack2(w6, w7);
#pragma unroll
        for (int r = 0; r < 32; ++r) {
            ulonglong2 f01 = *reinterpret_cast<const ulonglong2*>(&sf[r][kt]);
            ulonglong2 f45 = *reinterpret_cast<const ulonglong2*>(&sf[r][kt + 4]);
            fma2(acc[r], f01.x, p01);
            fma2(acc[r], f01.y, p23);
            fma2(acc[r], f45.x, p45);
            fma2(acc[r], f45.y, p67);
        }
    }
#pragma unroll
    for (int r = 0; r < 32; ++r) {
        int row = row0 + r;
        if (row < n) g_h[(size_t)row * D + c] = f2sum(acc[r]);
    }
}

// ---------------------------------------------------------------------------
// Kernel B: per-node soft-medoid aggregation. One 128-thread block per node.
// Gram via bf16 hi/lo mma.sync (error-compensated), rest fp32.
// ---------------------------------------------------------------------------
__device__ __forceinline__ float warp_max32(float v) {
#pragma unroll
    for (int off = 16; off > 0; off >>= 1)
        v = fmaxf(v, __shfl_xor_sync(0xffffffffu, v, off));
    return v;
}
__device__ __forceinline__ float warp_sum32(float v) {
#pragma unroll
    for (int off = 16; off > 0; off >>= 1)
        v += __shfl_xor_sync(0xffffffffu, v, off);
    return v;
}
__device__ __forceinline__ unsigned bf2u(__nv_bfloat16 a, __nv_bfloat16 b) {
    __nv_bfloat162 p = __halves2bfloat162(a, b);
    return *reinterpret_cast<unsigned*>(&p);
}

__global__ __launch_bounds__(128) void node_kernel(const void* __restrict__ top_k_idx,
                                                   const float* __restrict__ top_k_w,
                                                   const float* __restrict__ bias,
                                                   float* __restrict__ out,
                                                   int n) {
    __shared__ unsigned short Ahi[KN][ASTRIDE];   // bf16 bits
    __shared__ unsigned short Alo[KN][ASTRIDE];
    __shared__ float  gram[KN][33];
    __shared__ float  s_w[KN], s_sq[KN], s_r[KN];
    __shared__ int    s_idx[KN], s_mask[KN], s_is64;

    const int node = blockIdx.x;
    const int tid  = threadIdx.x;
    const int lane = tid & 31;
    const int warp = tid >> 5;

    // ---- per-block dtype detection on the first 128 bytes of the idx buffer
    // (a valid window under both int32 and int64 layouts) ----
    if (warp == 0) {
        int bad = 0;
        if (lane < 16) {
            long long v = reinterpret_cast<const long long*>(top_k_idx)[lane];
            bad = (v < -1 || v >= (long long)n);
        }
        unsigned any_bad = __ballot_sync(0xffffffffu, bad);
        if (lane == 0) s_is64 = (any_bad == 0u);
    }
    __syncthreads();

    if (tid < KN) {
        long long id;
        if (s_is64) {
            id = reinterpret_cast<const long long*>(top_k_idx)[(size_t)node * KN + tid];
        } else {
            id = (long long)reinterpret_cast<const int*>(top_k_idx)[(size_t)node * KN + tid];
        }
        int m = (id < 0);
        int ii = m ? 0 : (int)id;
        if (ii >= n) ii = 0;
        s_mask[tid] = m;
        s_idx[tid]  = ii;
        s_w[tid]    = m ? 0.f : top_k_w[(size_t)node * KN + tid];
    }
    __syncthreads();

    // ---- gather + fp32 -> bf16 hi/lo split ----
#pragma unroll
    for (int it = 0; it < 8; ++it) {
        int lin = it * 128 + tid;
        int r = lin >> 5, c = lin & 31;   // c = float4 index
        float4 v = reinterpret_cast<const float4*>(g_h + (size_t)s_idx[r] * D)[c];

        __nv_bfloat16 hx = __float2bfloat16_rn(v.x);
        __nv_bfloat16 hy = __float2bfloat16_rn(v.y);
        __nv_bfloat16 hz = __float2bfloat16_rn(v.z);
        __nv_bfloat16 hw = __float2bfloat16_rn(v.w);
        __nv_bfloat16 lx = __float2bfloat16_rn(v.x - __bfloat162float(hx));
        __nv_bfloat16 ly = __float2bfloat16_rn(v.y - __bfloat162float(hy));
        __nv_bfloat16 lz = __float2bfloat16_rn(v.z - __bfloat162float(hz));
        __nv_bfloat16 lw = __float2bfloat16_rn(v.w - __bfloat162float(hw));

        uint2 hv = make_uint2(bf2u(hx, hy), bf2u(hz, hw));
        uint2 lv = make_uint2(bf2u(lx, ly), bf2u(lz, lw));
        *reinterpret_cast<uint2*>(&Ahi[r][c * 4]) = hv;
        *reinterpret_cast<uint2*>(&Alo[r][c * 4]) = lv;
    }
    __syncthreads();

    // ---- Gram via mma.sync: warp w computes m-tile (w&1)*16, n-tiles (w>>1)*16 + {0,8}
    {
        const int m0 = (warp & 1) * 16;
        const int nb = (warp >> 1) * 16;

        float acc[2][4] = {{0.f, 0.f, 0.f, 0.f}, {0.f, 0.f, 0.f, 0.f}};

        // per-lane ldmatrix row/col offsets
        const int a_row = m0 + (lane & 7) + 8 * ((lane >> 3) & 1);
        const int a_colsel = 8 * (lane >> 4);
        const int b_row0 = nb + (lane & 7);            // n-tile 0
        const int b_row1 = nb + 8 + (lane & 7);        // n-tile 1
        const int b_colsel = 8 * ((lane >> 3) & 1);

        unsigned hiBase = (unsigned)__cvta_generic_to_shared(&Ahi[0][0]);
        unsigned loBase = (unsigned)__cvta_generic_to_shared(&Alo[0][0]);

#pragma unroll
        for (int kk = 0; kk < D; kk += 16) {
            unsigned aoff = (unsigned)((a_row * ASTRIDE + kk + a_colsel) * 2);
            unsigned b0off = (unsigned)((b_row0 * ASTRIDE + kk + b_colsel) * 2);
            unsigned b1off = (unsigned)((b_row1 * ASTRIDE + kk + b_colsel) * 2);

            unsigned ahi[4], alo[4], bhi0[2], blo0[2], bhi1[2], blo1[2];
            ldm_x4(ahi, hiBase + aoff);
            ldm_x4(alo, loBase + aoff);
            ldm_x2(bhi0, hiBase + b0off);
            ldm_x2(blo0, loBase + b0off);
            ldm_x2(bhi1, hiBase + b1off);
            ldm_x2(blo1, loBase + b1off);

            mma_bf16(acc[0], ahi, bhi0);
            mma_bf16(acc[0], ahi, blo0);
            mma_bf16(acc[0], alo, bhi0);
            mma_bf16(acc[1], ahi, bhi1);
            mma_bf16(acc[1], ahi, blo1);
            mma_bf16(acc[1], alo, bhi1);
        }

        // epilogue: write gram
        const int er = m0 + (lane >> 2);
        const int ec = (lane & 3) * 2;
#pragma unroll
        for (int t = 0; t < 2; ++t) {
            int cc = nb + t * 8 + ec;
            gram[er][cc]         = acc[t][0];
            gram[er][cc + 1]     = acc[t][1];
            gram[er + 8][cc]     = acc[t][2];
            gram[er + 8][cc + 1] = acc[t][3];
        }
    }
    __syncthreads();

    // ---- squared norms from the diagonal ----
    if (tid < KN) s_sq[tid] = gram[tid][tid];
    __syncthreads();

    // ---- distances (in place over gram) ----
#pragma unroll
    for (int e = 0; e < 8; ++e) {
        int lin = e * 128 + tid;
        int k = lin >> 5, m = lin & 31;
        float d2 = s_sq[k] + s_sq[m] - 2.f * gram[k][m];
        float dv = (d2 > 0.f) ? sqrtf(d2) : 0.f;
        if (s_mask[k] | s_mask[m]) dv = 0.f;
        gram[k][m] = dv;
    }
    __syncthreads();

    // ---- dagg + softmax + weight correction (warp 0) ----
    if (tid < KN) {
        float s = 0.f;
#pragma unroll
        for (int m = 0; m < KN; ++m) s += s_w[m] * gram[tid][m];
        if (s_mask[tid] || !isfinite(s)) s = FLT_MAX;

        float neg = -s;  // TEMPERATURE = 1
        float mx  = warp_max32(neg);
        float ev  = __expf(neg - mx);
        float se  = warp_sum32(ev);
        float r   = ev / se;
        r *= s_w[tid];
        float sr = warp_sum32(r);
        r = r / sr;
        if (s_mask[tid]) r = 0.f;
        s_r[tid] = r;
    }
    __syncthreads();

    // ---- out[node][d] = sum_k r[k] * (hi[k][d] + lo[k][d]) + bias[d] ----
    {
        float acc = 0.f;
#pragma unroll
        for (int k = 0; k < KN; ++k) {
            __nv_bfloat16 h = *reinterpret_cast<const __nv_bfloat16*>(&Ahi[k][tid]);
            __nv_bfloat16 l = *reinterpret_cast<const __nv_bfloat16*>(&Alo[k][tid]);
            float fv = __bfloat162float(h) + __bfloat162float(l);
            acc += s_r[k] * fv;
        }
        out[(size_t)node * D + tid] = acc + bias[tid];
    }
}

// ---------------------------------------------------------------------------
extern "C" void kernel_launch(void* const* d_in, const int* in_sizes, int n_in,
                              void* d_out, int out_size) {
    const float* feat   = (const float*)d_in[0];      // [n, 128]
    const float* weight = (const float*)d_in[1];      // [128, 128]
    const float* bias   = (const float*)d_in[2];      // [128]
    const float* tkw    = (const float*)d_in[3];      // [n, 32]
    const void*  tki    = d_in[4];                    // [n, 32] int32 or int64

    float* out = (float*)d_out;
    const int n = in_sizes[0] / D;

    proj_kernel<<<(n + 31) / 32, 128>>>(feat, weight, n);
    node_kernel<<<n, 128>>>(tki, tkw, bias, out, n);
}

// round 7
// speedup vs baseline: 1.9419x; 1.1050x over previous
#include <cuda_runtime.h>
#include <cuda_bf16.h>
#include <float.h>

#define D 128
#define KN 32
#define MAXN 50000
#define ASTRIDE 136   // bf16 elements per row (128 + 8 pad) -> 272 B row stride
#define FULLM 0xffffffffu

// scratch for projected features h = feat @ weight
__device__ float g_h[(size_t)MAXN * D];

// ---- packed fp32x2 helpers (proj kernel) ----
__device__ __forceinline__ void fma2(unsigned long long& d,
                                     unsigned long long a,
                                     unsigned long long b) {
    asm("fma.rn.f32x2 %0, %1, %2, %0;" : "+l"(d) : "l"(a), "l"(b));
}
__device__ __forceinline__ unsigned long long pack2(float lo, float hi) {
    unsigned long long r;
    asm("mov.b64 %0, {%1, %2};" : "=l"(r) : "f"(lo), "f"(hi));
    return r;
}
__device__ __forceinline__ float f2sum(unsigned long long v) {
    float lo = __uint_as_float((unsigned)(v & 0xffffffffull));
    float hi = __uint_as_float((unsigned)(v >> 32));
    return lo + hi;
}

// ---- mma / ldmatrix helpers ----
__device__ __forceinline__ void ldm_x4(unsigned (&r)[4], unsigned addr) {
    asm volatile("ldmatrix.sync.aligned.m8n8.x4.shared.b16 {%0,%1,%2,%3}, [%4];"
                 : "=r"(r[0]), "=r"(r[1]), "=r"(r[2]), "=r"(r[3]) : "r"(addr));
}
__device__ __forceinline__ void mma4(float* d, const unsigned* a,
                                     unsigned b0, unsigned b1) {
    asm volatile(
        "mma.sync.aligned.m16n8k16.row.col.f32.bf16.bf16.f32 "
        "{%0,%1,%2,%3},{%4,%5,%6,%7},{%8,%9},{%0,%1,%2,%3};"
        : "+f"(d[0]), "+f"(d[1]), "+f"(d[2]), "+f"(d[3])
        : "r"(a[0]), "r"(a[1]), "r"(a[2]), "r"(a[3]), "r"(b0), "r"(b1));
}

__device__ __forceinline__ float warp_max32(float v) {
#pragma unroll
    for (int off = 16; off > 0; off >>= 1)
        v = fmaxf(v, __shfl_xor_sync(FULLM, v, off));
    return v;
}
__device__ __forceinline__ float warp_sum32(float v) {
#pragma unroll
    for (int off = 16; off > 0; off >>= 1)
        v += __shfl_xor_sync(FULLM, v, off);
    return v;
}
__device__ __forceinline__ unsigned bf2u(__nv_bfloat16 a, __nv_bfloat16 b) {
    __nv_bfloat162 p = __halves2bfloat162(a, b);
    return *reinterpret_cast<unsigned*>(&p);
}

// ---------------------------------------------------------------------------
// Kernel A: h[n, 128] = feat[n, 128] @ weight[128, 128]   (f32x2 inner loop)
// ---------------------------------------------------------------------------
__global__ __launch_bounds__(128) void proj_kernel(const float* __restrict__ feat,
                                                   const float* __restrict__ weight,
                                                   int n) {
    __shared__ float sf[32][D];
    const int row0 = blockIdx.x * 32;
    const int tid  = threadIdx.x;

#pragma unroll
    for (int it = 0; it < 8; ++it) {
        int lin = it * 128 + tid;
        int r = lin >> 5, c = lin & 31;
        int row = row0 + r;
        float4 v = make_float4(0.f, 0.f, 0.f, 0.f);
        if (row < n) v = reinterpret_cast<const float4*>(feat)[(size_t)row * 32 + c];
        *reinterpret_cast<float4*>(&sf[r][c * 4]) = v;
    }
    __syncthreads();

    const int c = tid;
    unsigned long long acc[32];
#pragma unroll
    for (int r = 0; r < 32; ++r) acc[r] = 0ull;

#pragma unroll 4
    for (int kt = 0; kt < D; kt += 8) {
        float w0 = weight[(kt + 0) * D + c];
        float w1 = weight[(kt + 1) * D + c];
        float w2 = weight[(kt + 2) * D + c];
        float w3 = weight[(kt + 3) * D + c];
        float w4 = weight[(kt + 4) * D + c];
        float w5 = weight[(kt + 5) * D + c];
        float w6 = weight[(kt + 6) * D + c];
        float w7 = weight[(kt + 7) * D + c];
        unsigned long long p01 = pack2(w0, w1);
        unsigned long long p23 = pack2(w2, w3);
        unsigned long long p45 = pack2(w4, w5);
        unsigned long long p67 = pack2(w6, w7);
#pragma unroll
        for (int r = 0; r < 32; ++r) {
            ulonglong2 f01 = *reinterpret_cast<const ulonglong2*>(&sf[r][kt]);
            ulonglong2 f45 = *reinterpret_cast<const ulonglong2*>(&sf[r][kt + 4]);
            fma2(acc[r], f01.x, p01);
            fma2(acc[r], f01.y, p23);
            fma2(acc[r], f45.x, p45);
            fma2(acc[r], f45.y, p67);
        }
    }
#pragma unroll
    for (int r = 0; r < 32; ++r) {
        int row = row0 + r;
        if (row < n) g_h[(size_t)row * D + c] = f2sum(acc[r]);
    }
}

// ---------------------------------------------------------------------------
// Kernel B: one WARP per node (2 warps / 64-thread block), fully
// warp-synchronous. Gram in registers via bf16 hi/lo mma.sync, fragments
// shared between A and B sides (symmetric product).
// ---------------------------------------------------------------------------
__global__ __launch_bounds__(64, 6) void node_kernel(const void* __restrict__ top_k_idx,
                                                     const float* __restrict__ top_k_w,
                                                     const float* __restrict__ bias,
                                                     float* __restrict__ out,
                                                     int n) {
    __shared__ __align__(16) unsigned short Ahi[2][KN][ASTRIDE];
    __shared__ __align__(16) unsigned short Alo[2][KN][ASTRIDE];
    __shared__ float s_sq[2][KN];
    __shared__ float s_dagg[2][KN];

    const int warp = threadIdx.x >> 5;
    const int lane = threadIdx.x & 31;
    const int node = blockIdx.x * 2 + warp;
    if (node >= n) return;

    // ---- dtype detection on first 128 B of idx buffer (valid either way) ----
    int bad = 0;
    if (lane < 16) {
        long long v = reinterpret_cast<const long long*>(top_k_idx)[lane];
        bad = (v < -1 || v >= (long long)n);
    }
    const bool is64 = (__ballot_sync(FULLM, bad) == 0u);

    // ---- per-lane neighbor meta (k = lane) ----
    long long id = is64
        ? reinterpret_cast<const long long*>(top_k_idx)[(size_t)node * KN + lane]
        : (long long)reinterpret_cast<const int*>(top_k_idx)[(size_t)node * KN + lane];
    const int msk = (id < 0);
    int nbr = msk ? 0 : (int)id;
    if (nbr >= n) nbr = 0;
    const float wgt = msk ? 0.f : top_k_w[(size_t)node * KN + lane];

    unsigned short (*ahi)[ASTRIDE] = Ahi[warp];
    unsigned short (*alo)[ASTRIDE] = Alo[warp];

    // ---- gather + fp32 -> bf16 hi/lo split (row r, cols lane*4..+3) ----
#pragma unroll 4
    for (int r = 0; r < KN; ++r) {
        int src = __shfl_sync(FULLM, nbr, r);
        float4 v = reinterpret_cast<const float4*>(g_h + (size_t)src * D)[lane];

        __nv_bfloat16 hx = __float2bfloat16_rn(v.x);
        __nv_bfloat16 hy = __float2bfloat16_rn(v.y);
        __nv_bfloat16 hz = __float2bfloat16_rn(v.z);
        __nv_bfloat16 hw = __float2bfloat16_rn(v.w);
        __nv_bfloat16 lx = __float2bfloat16_rn(v.x - __bfloat162float(hx));
        __nv_bfloat16 ly = __float2bfloat16_rn(v.y - __bfloat162float(hy));
        __nv_bfloat16 lz = __float2bfloat16_rn(v.z - __bfloat162float(hz));
        __nv_bfloat16 lw = __float2bfloat16_rn(v.w - __bfloat162float(hw));

        *reinterpret_cast<uint2*>(&ahi[r][lane * 4]) =
            make_uint2(bf2u(hx, hy), bf2u(hz, hw));
        *reinterpret_cast<uint2*>(&alo[r][lane * 4]) =
            make_uint2(bf2u(lx, ly), bf2u(lz, lw));
    }
    __syncwarp();

    // ---- full 32x32 Gram in registers ----
    // ldm x4 of a 16-row tile serves as BOTH the A fragment and the two
    // 8-row B fragments ({r0,r2} and {r1,r3}) of the same tile.
    float acc[2][4][4];
#pragma unroll
    for (int a = 0; a < 2; ++a)
#pragma unroll
        for (int b = 0; b < 4; ++b)
#pragma unroll
            for (int i = 0; i < 4; ++i) acc[a][b][i] = 0.f;

    const int trow = (lane & 7) + 8 * ((lane >> 3) & 1);
    const int tcol = 8 * (lane >> 4);
    const unsigned hiB = (unsigned)__cvta_generic_to_shared(&ahi[0][0]);
    const unsigned loB = (unsigned)__cvta_generic_to_shared(&alo[0][0]);

#pragma unroll
    for (int kk = 0; kk < D; kk += 16) {
        unsigned o0 = (unsigned)((trow * ASTRIDE + kk + tcol) * 2);
        unsigned o1 = (unsigned)(((16 + trow) * ASTRIDE + kk + tcol) * 2);
        unsigned h0[4], h1[4], l0[4], l1[4];
        ldm_x4(h0, hiB + o0);
        ldm_x4(h1, hiB + o1);
        ldm_x4(l0, loB + o0);
        ldm_x4(l1, loB + o1);

#pragma unroll
        for (int mt = 0; mt < 2; ++mt) {
            const unsigned* Ah = mt ? h1 : h0;
            const unsigned* Al = mt ? l1 : l0;
#pragma unroll
            for (int nt = 0; nt < 4; ++nt) {
                const unsigned* Bh = (nt < 2) ? h0 : h1;
                const unsigned* Bl = (nt < 2) ? l0 : l1;
                unsigned bh0 = (nt & 1) ? Bh[1] : Bh[0];
                unsigned bh1 = (nt & 1) ? Bh[3] : Bh[2];
                unsigned bl0 = (nt & 1) ? Bl[1] : Bl[0];
                unsigned bl1 = (nt & 1) ? Bl[3] : Bl[2];
                mma4(acc[mt][nt], Ah, bh0, bh1);   // hi*hi
                mma4(acc[mt][nt], Ah, bl0, bl1);   // hi*lo
                mma4(acc[mt][nt], Al, bh0, bh1);   // lo*hi
            }
        }
    }

    // lane's element map: acc[mt][nt][h*2+j] = gram[mt*16 + er + h*8][nt*8 + ec + j]
    const int er = lane >> 2;
    const int ec = (lane & 3) * 2;

    // ---- diagonal -> s_sq ----
#pragma unroll
    for (int mt = 0; mt < 2; ++mt)
#pragma unroll
        for (int nt = 0; nt < 4; ++nt)
#pragma unroll
            for (int i = 0; i < 4; ++i) {
                int rg = mt * 16 + er + ((i >> 1) << 3);
                int cg = nt * 8 + ec + (i & 1);
                if (rg == cg) s_sq[warp][rg] = acc[mt][nt][i];
            }
    __syncwarp();

    // ---- dist + dagg partials in registers ----
    float dp[4] = {0.f, 0.f, 0.f, 0.f};  // rows: er, er+8, 16+er, 24+er
    const float sqr[4] = { s_sq[warp][er],      s_sq[warp][er + 8],
                           s_sq[warp][16 + er], s_sq[warp][24 + er] };
#pragma unroll
    for (int nt = 0; nt < 4; ++nt) {
#pragma unroll
        for (int j = 0; j < 2; ++j) {
            int cg = nt * 8 + ec + j;
            float sqc = s_sq[warp][cg];
            float wc  = __shfl_sync(FULLM, wgt, cg);   // 0 for masked cols
#pragma unroll
            for (int mt = 0; mt < 2; ++mt) {
#pragma unroll
                for (int h = 0; h < 2; ++h) {
                    float g  = acc[mt][nt][h * 2 + j];
                    float d2 = sqr[mt * 2 + h] + sqc - 2.f * g;
                    float dv = (d2 > 0.f) ? sqrtf(d2) : 0.f;
                    dp[mt * 2 + h] += wc * dv;
                }
            }
        }
    }
    // reduce over the 4 lanes of each quad (covers all 32 columns)
#pragma unroll
    for (int q = 0; q < 4; ++q) {
        dp[q] += __shfl_xor_sync(FULLM, dp[q], 1);
        dp[q] += __shfl_xor_sync(FULLM, dp[q], 2);
    }
    if ((lane & 3) == 0) {
        s_dagg[warp][er]      = dp[0];
        s_dagg[warp][er + 8]  = dp[1];
        s_dagg[warp][16 + er] = dp[2];
        s_dagg[warp][24 + er] = dp[3];
    }
    __syncwarp();

    // ---- softmax + weight correction (k = lane) ----
    float dg = s_dagg[warp][lane];
    if (msk || !isfinite(dg)) dg = FLT_MAX;
    float neg = -dg;                      // TEMPERATURE = 1
    float mx  = warp_max32(neg);
    float ev  = __expf(neg - mx);
    float se  = warp_sum32(ev);
    float rr  = ev / se;
    rr *= wgt;
    float sr = warp_sum32(rr);
    rr = rr / sr;
    if (msk) rr = 0.f;

    // ---- out[node][d] = sum_k r[k]*(hi+lo)[k][d] + bias[d]; d = lane*4..+3 ----
    float4 b4 = reinterpret_cast<const float4*>(bias)[lane];
    float o0 = 0.f, o1 = 0.f, o2 = 0.f, o3 = 0.f;
#pragma unroll 8
    for (int k = 0; k < KN; ++k) {
        float rk = __shfl_sync(FULLM, rr, k);
        uint2 hv = *reinterpret_cast<const uint2*>(&ahi[k][lane * 4]);
        uint2 lv = *reinterpret_cast<const uint2*>(&alo[k][lane * 4]);
        __nv_bfloat162 h01 = *reinterpret_cast<__nv_bfloat162*>(&hv.x);
        __nv_bfloat162 h23 = *reinterpret_cast<__nv_bfloat162*>(&hv.y);
        __nv_bfloat162 l01 = *reinterpret_cast<__nv_bfloat162*>(&lv.x);
        __nv_bfloat162 l23 = *reinterpret_cast<__nv_bfloat162*>(&lv.y);
        o0 += rk * (__low2float(h01)  + __low2float(l01));
        o1 += rk * (__high2float(h01) + __high2float(l01));
        o2 += rk * (__low2float(h23)  + __low2float(l23));
        o3 += rk * (__high2float(h23) + __high2float(l23));
    }
    reinterpret_cast<float4*>(out)[(size_t)node * 32 + lane] =
        make_float4(o0 + b4.x, o1 + b4.y, o2 + b4.z, o3 + b4.w);
}

// ---------------------------------------------------------------------------
extern "C" void kernel_launch(void* const* d_in, const int* in_sizes, int n_in,
                              void* d_out, int out_size) {
    const float* feat   = (const float*)d_in[0];      // [n, 128]
    const float* weight = (const float*)d_in[1];      // [128, 128]
    const float* bias   = (const float*)d_in[2];      // [128]
    const float* tkw    = (const float*)d_in[3];      // [n, 32]
    const void*  tki    = d_in[4];                    // [n, 32] int32 or int64

    float* out = (float*)d_out;
    const int n = in_sizes[0] / D;

    proj_kernel<<<(n + 31) / 32, 128>>>(feat, weight, n);
    node_kernel<<<(n + 1) / 2, 64>>>(tki, tkw, bias, out, n);
}

// round 8
// speedup vs baseline: 2.4737x; 1.2739x over previous
#include <cuda_runtime.h>
#include <cuda_bf16.h>
#include <float.h>

#define D 128
#define KN 32
#define MAXN 50000
#define CSTR 72       // bf16 elems per chunk row (64 + 8 pad) -> 144 B stride
#define FULLM 0xffffffffu

// scratch for projected features h = feat @ weight
__device__ float g_h[(size_t)MAXN * D];

// ---- packed fp32x2 helpers (proj kernel) ----
__device__ __forceinline__ void fma2(unsigned long long& d,
                                     unsigned long long a,
                                     unsigned long long b) {
    asm("fma.rn.f32x2 %0, %1, %2, %0;" : "+l"(d) : "l"(a), "l"(b));
}
__device__ __forceinline__ unsigned long long pack2(float lo, float hi) {
    unsigned long long r;
    asm("mov.b64 %0, {%1, %2};" : "=l"(r) : "f"(lo), "f"(hi));
    return r;
}
__device__ __forceinline__ float f2sum(unsigned long long v) {
    float lo = __uint_as_float((unsigned)(v & 0xffffffffull));
    float hi = __uint_as_float((unsigned)(v >> 32));
    return lo + hi;
}

// ---- mma / ldmatrix helpers ----
__device__ __forceinline__ void ldm_x4(unsigned (&r)[4], unsigned addr) {
    asm volatile("ldmatrix.sync.aligned.m8n8.x4.shared.b16 {%0,%1,%2,%3}, [%4];"
                 : "=r"(r[0]), "=r"(r[1]), "=r"(r[2]), "=r"(r[3]) : "r"(addr));
}
__device__ __forceinline__ void mma4(float* d, const unsigned* a,
                                     unsigned b0, unsigned b1) {
    asm volatile(
        "mma.sync.aligned.m16n8k16.row.col.f32.bf16.bf16.f32 "
        "{%0,%1,%2,%3},{%4,%5,%6,%7},{%8,%9},{%0,%1,%2,%3};"
        : "+f"(d[0]), "+f"(d[1]), "+f"(d[2]), "+f"(d[3])
        : "r"(a[0]), "r"(a[1]), "r"(a[2]), "r"(a[3]), "r"(b0), "r"(b1));
}

__device__ __forceinline__ float warp_max32(float v) {
#pragma unroll
    for (int off = 16; off > 0; off >>= 1)
        v = fmaxf(v, __shfl_xor_sync(FULLM, v, off));
    return v;
}
__device__ __forceinline__ float warp_sum32(float v) {
#pragma unroll
    for (int off = 16; off > 0; off >>= 1)
        v += __shfl_xor_sync(FULLM, v, off);
    return v;
}
__device__ __forceinline__ unsigned bf2u(__nv_bfloat16 a, __nv_bfloat16 b) {
    __nv_bfloat162 p = __halves2bfloat162(a, b);
    return *reinterpret_cast<unsigned*>(&p);
}

// ---------------------------------------------------------------------------
// Kernel A: h[n, 128] = feat[n, 128] @ weight[128, 128]   (f32x2 inner loop)
// ---------------------------------------------------------------------------
__global__ __launch_bounds__(128) void proj_kernel(const float* __restrict__ feat,
                                                   const float* __restrict__ weight,
                                                   int n) {
    __shared__ float sf[32][D];
    const int row0 = blockIdx.x * 32;
    const int tid  = threadIdx.x;

#pragma unroll
    for (int it = 0; it < 8; ++it) {
        int lin = it * 128 + tid;
        int r = lin >> 5, c = lin & 31;
        int row = row0 + r;
        float4 v = make_float4(0.f, 0.f, 0.f, 0.f);
        if (row < n) v = reinterpret_cast<const float4*>(feat)[(size_t)row * 32 + c];
        *reinterpret_cast<float4*>(&sf[r][c * 4]) = v;
    }
    __syncthreads();

    const int c = tid;
    unsigned long long acc[32];
#pragma unroll
    for (int r = 0; r < 32; ++r) acc[r] = 0ull;

#pragma unroll 4
    for (int kt = 0; kt < D; kt += 8) {
        float w0 = weight[(kt + 0) * D + c];
        float w1 = weight[(kt + 1) * D + c];
        float w2 = weight[(kt + 2) * D + c];
        float w3 = weight[(kt + 3) * D + c];
        float w4 = weight[(kt + 4) * D + c];
        float w5 = weight[(kt + 5) * D + c];
        float w6 = weight[(kt + 6) * D + c];
        float w7 = weight[(kt + 7) * D + c];
        unsigned long long p01 = pack2(w0, w1);
        unsigned long long p23 = pack2(w2, w3);
        unsigned long long p45 = pack2(w4, w5);
        unsigned long long p67 = pack2(w6, w7);
#pragma unroll
        for (int r = 0; r < 32; ++r) {
            ulonglong2 f01 = *reinterpret_cast<const ulonglong2*>(&sf[r][kt]);
            ulonglong2 f45 = *reinterpret_cast<const ulonglong2*>(&sf[r][kt + 4]);
            fma2(acc[r], f01.x, p01);
            fma2(acc[r], f01.y, p23);
            fma2(acc[r], f45.x, p45);
            fma2(acc[r], f45.y, p67);
        }
    }
#pragma unroll
    for (int r = 0; r < 32; ++r) {
        int row = row0 + r;
        if (row < n) g_h[(size_t)row * D + c] = f2sum(acc[r]);
    }
}

// ---------------------------------------------------------------------------
// Kernel B: one WARP per node, warp-synchronous. Gram accumulated over two
// 64-wide D-chunks through a half-size smem tile (9 KB/node) for occupancy.
// Gram in registers via bf16 hi/lo mma; final sum re-reads fp32 from L2.
// ---------------------------------------------------------------------------
__global__ __launch_bounds__(64, 12) void node_kernel(const void* __restrict__ top_k_idx,
                                                      const float* __restrict__ top_k_w,
                                                      const float* __restrict__ bias,
                                                      float* __restrict__ out,
                                                      int n) {
    __shared__ __align__(16) unsigned short Ahi[2][KN][CSTR];
    __shared__ __align__(16) unsigned short Alo[2][KN][CSTR];
    __shared__ float s_sq[2][KN];
    __shared__ float s_dagg[2][KN];

    const int warp = threadIdx.x >> 5;
    const int lane = threadIdx.x & 31;
    const int node = blockIdx.x * 2 + warp;
    if (node >= n) return;

    // ---- dtype detection on first 128 B of idx buffer (valid either way) ----
    int bad = 0;
    if (lane < 16) {
        long long v = reinterpret_cast<const long long*>(top_k_idx)[lane];
        bad = (v < -1 || v >= (long long)n);
    }
    const bool is64 = (__ballot_sync(FULLM, bad) == 0u);

    // ---- per-lane neighbor meta (k = lane) ----
    long long id = is64
        ? reinterpret_cast<const long long*>(top_k_idx)[(size_t)node * KN + lane]
        : (long long)reinterpret_cast<const int*>(top_k_idx)[(size_t)node * KN + lane];
    const int msk = (id < 0);
    int nbr = msk ? 0 : (int)id;
    if (nbr >= n) nbr = 0;
    const float wgt = msk ? 0.f : top_k_w[(size_t)node * KN + lane];

    unsigned short (*ahi)[CSTR] = Ahi[warp];
    unsigned short (*alo)[CSTR] = Alo[warp];

    // fragment accumulators for the full 32x32 Gram
    float acc[2][4][4];
#pragma unroll
    for (int a = 0; a < 2; ++a)
#pragma unroll
        for (int b = 0; b < 4; ++b)
#pragma unroll
            for (int i = 0; i < 4; ++i) acc[a][b][i] = 0.f;

    const int trow = (lane & 7) + 8 * ((lane >> 3) & 1);
    const int tcol = 8 * (lane >> 4);
    const unsigned hiB = (unsigned)__cvta_generic_to_shared(&ahi[0][0]);
    const unsigned loB = (unsigned)__cvta_generic_to_shared(&alo[0][0]);

    const int gr_half = lane >> 4;        // which of the row pair
    const int gr_c4   = lane & 15;        // float4 col within 64-wide chunk

#pragma unroll
    for (int chunk = 0; chunk < 2; ++chunk) {
        // ---- gather chunk + fp32 -> bf16 hi/lo split ----
        // rows 2*it + gr_half, cols gr_c4*4 .. +3 of this 64-wide chunk
#pragma unroll 4
        for (int it = 0; it < 16; ++it) {
            int r = it * 2 + gr_half;
            int src = __shfl_sync(FULLM, nbr, r);
            float4 v = reinterpret_cast<const float4*>(
                g_h + (size_t)src * D + chunk * 64)[gr_c4];

            __nv_bfloat16 hx = __float2bfloat16_rn(v.x);
            __nv_bfloat16 hy = __float2bfloat16_rn(v.y);
            __nv_bfloat16 hz = __float2bfloat16_rn(v.z);
            __nv_bfloat16 hw = __float2bfloat16_rn(v.w);
            __nv_bfloat16 lx = __float2bfloat16_rn(v.x - __bfloat162float(hx));
            __nv_bfloat16 ly = __float2bfloat16_rn(v.y - __bfloat162float(hy));
            __nv_bfloat16 lz = __float2bfloat16_rn(v.z - __bfloat162float(hz));
            __nv_bfloat16 lw = __float2bfloat16_rn(v.w - __bfloat162float(hw));

            *reinterpret_cast<uint2*>(&ahi[r][gr_c4 * 4]) =
                make_uint2(bf2u(hx, hy), bf2u(hz, hw));
            *reinterpret_cast<uint2*>(&alo[r][gr_c4 * 4]) =
                make_uint2(bf2u(lx, ly), bf2u(lz, lw));
        }
        __syncwarp();

        // ---- mma-accumulate this chunk (k = 0..63) ----
#pragma unroll
        for (int kk = 0; kk < 64; kk += 16) {
            unsigned o0 = (unsigned)((trow * CSTR + kk + tcol) * 2);
            unsigned o1 = (unsigned)(((16 + trow) * CSTR + kk + tcol) * 2);
            unsigned h0[4], h1[4], l0[4], l1[4];
            ldm_x4(h0, hiB + o0);
            ldm_x4(h1, hiB + o1);
            ldm_x4(l0, loB + o0);
            ldm_x4(l1, loB + o1);

#pragma unroll
            for (int mt = 0; mt < 2; ++mt) {
                const unsigned* Ah = mt ? h1 : h0;
                const unsigned* Al = mt ? l1 : l0;
#pragma unroll
                for (int nt = 0; nt < 4; ++nt) {
                    const unsigned* Bh = (nt < 2) ? h0 : h1;
                    const unsigned* Bl = (nt < 2) ? l0 : l1;
                    unsigned bh0 = (nt & 1) ? Bh[1] : Bh[0];
                    unsigned bh1 = (nt & 1) ? Bh[3] : Bh[2];
                    unsigned bl0 = (nt & 1) ? Bl[1] : Bl[0];
                    unsigned bl1 = (nt & 1) ? Bl[3] : Bl[2];
                    mma4(acc[mt][nt], Ah, bh0, bh1);   // hi*hi
                    mma4(acc[mt][nt], Ah, bl0, bl1);   // hi*lo
                    mma4(acc[mt][nt], Al, bh0, bh1);   // lo*hi
                }
            }
        }
        __syncwarp();   // done reading smem before next chunk overwrites
    }

    // lane's element map: acc[mt][nt][h*2+j] = gram[mt*16 + er + h*8][nt*8 + ec + j]
    const int er = lane >> 2;
    const int ec = (lane & 3) * 2;

    // ---- diagonal -> s_sq ----
#pragma unroll
    for (int mt = 0; mt < 2; ++mt)
#pragma unroll
        for (int nt = 0; nt < 4; ++nt)
#pragma unroll
            for (int i = 0; i < 4; ++i) {
                int rg = mt * 16 + er + ((i >> 1) << 3);
                int cg = nt * 8 + ec + (i & 1);
                if (rg == cg) s_sq[warp][rg] = acc[mt][nt][i];
            }
    __syncwarp();

    // ---- dist + dagg partials in registers ----
    float dp[4] = {0.f, 0.f, 0.f, 0.f};  // rows: er, er+8, 16+er, 24+er
    const float sqr[4] = { s_sq[warp][er],      s_sq[warp][er + 8],
                           s_sq[warp][16 + er], s_sq[warp][24 + er] };
#pragma unroll
    for (int nt = 0; nt < 4; ++nt) {
#pragma unroll
        for (int j = 0; j < 2; ++j) {
            int cg = nt * 8 + ec + j;
            float sqc = s_sq[warp][cg];
            float wc  = __shfl_sync(FULLM, wgt, cg);   // 0 for masked cols
#pragma unroll
            for (int mt = 0; mt < 2; ++mt) {
#pragma unroll
                for (int h = 0; h < 2; ++h) {
                    float g  = acc[mt][nt][h * 2 + j];
                    float d2 = sqr[mt * 2 + h] + sqc - 2.f * g;
                    float dv = (d2 > 0.f) ? sqrtf(d2) : 0.f;
                    dp[mt * 2 + h] += wc * dv;
                }
            }
        }
    }
#pragma unroll
    for (int q = 0; q < 4; ++q) {
        dp[q] += __shfl_xor_sync(FULLM, dp[q], 1);
        dp[q] += __shfl_xor_sync(FULLM, dp[q], 2);
    }
    if ((lane & 3) == 0) {
        s_dagg[warp][er]      = dp[0];
        s_dagg[warp][er + 8]  = dp[1];
        s_dagg[warp][16 + er] = dp[2];
        s_dagg[warp][24 + er] = dp[3];
    }
    __syncwarp();

    // ---- softmax + weight correction (k = lane) ----
    float dg = s_dagg[warp][lane];
    if (msk || !isfinite(dg)) dg = FLT_MAX;
    float neg = -dg;                      // TEMPERATURE = 1
    float mx  = warp_max32(neg);
    float ev  = __expf(neg - mx);
    float se  = warp_sum32(ev);
    float rr  = ev / se;
    rr *= wgt;
    float sr = warp_sum32(rr);
    rr = rr / sr;
    if (msk) rr = 0.f;

    // ---- out[node][d] = sum_k r[k] * h[idx_k][d] + bias[d]; fp32 from L2 ----
    float4 b4 = reinterpret_cast<const float4*>(bias)[lane];
    float o0 = 0.f, o1 = 0.f, o2 = 0.f, o3 = 0.f;
#pragma unroll 8
    for (int k = 0; k < KN; ++k) {
        float rk  = __shfl_sync(FULLM, rr, k);
        int   src = __shfl_sync(FULLM, nbr, k);
        float4 v = reinterpret_cast<const float4*>(g_h + (size_t)src * D)[lane];
        o0 += rk * v.x;
        o1 += rk * v.y;
        o2 += rk * v.z;
        o3 += rk * v.w;
    }
    reinterpret_cast<float4*>(out)[(size_t)node * 32 + lane] =
        make_float4(o0 + b4.x, o1 + b4.y, o2 + b4.z, o3 + b4.w);
}

// ---------------------------------------------------------------------------
extern "C" void kernel_launch(void* const* d_in, const int* in_sizes, int n_in,
                              void* d_out, int out_size) {
    const float* feat   = (const float*)d_in[0];      // [n, 128]
    const float* weight = (const float*)d_in[1];      // [128, 128]
    const float* bias   = (const float*)d_in[2];      // [128]
    const float* tkw    = (const float*)d_in[3];      // [n, 32]
    const void*  tki    = d_in[4];                    // [n, 32] int32 or int64

    float* out = (float*)d_out;
    const int n = in_sizes[0] / D;

    proj_kernel<<<(n + 31) / 32, 128>>>(feat, weight, n);
    node_kernel<<<(n + 1) / 2, 64>>>(tki, tkw, bias, out, n);
}